// round 16
// baseline (speedup 1.0000x reference)
#include <cuda_runtime.h>
#include <cuda_bf16.h>
#include <math.h>
#include <stdint.h>

// Problem constants
#define Bc   2
#define Sc   2048
#define Ec   1024
#define Hc   16
#define HDc  64
#define Mrows (Bc*Sc)          // 4096
#define NEGBIG (-1.0e9f)
#define FULLM 0xffffffffu

// Scratch (device globals; no allocation allowed)
__device__ float g_q[Bc*Hc*Sc*HDc];     // [B,H,S,HD]
__device__ float g_k[Bc*Hc*Sc*HDc];
__device__ float g_v[Bc*Hc*Sc*HDc];
__device__ float g_vals[Mrows*Ec];      // [B,S,E]

// ---------------------------------------------------------------------------
// mma.sync helpers
// ---------------------------------------------------------------------------
__device__ __forceinline__ uint32_t f2tf(float x) {
    uint32_t r;
    asm("cvt.rna.tf32.f32 %0, %1;" : "=r"(r) : "f"(x));
    return r;
}
__device__ __forceinline__ void mma8(float* c,
    uint32_t a0, uint32_t a1, uint32_t a2, uint32_t a3,
    uint32_t b0, uint32_t b1)
{
    asm volatile(
        "mma.sync.aligned.m16n8k8.row.col.f32.tf32.tf32.f32 "
        "{%0,%1,%2,%3},{%4,%5,%6,%7},{%8,%9},{%0,%1,%2,%3};"
        : "+f"(c[0]), "+f"(c[1]), "+f"(c[2]), "+f"(c[3])
        : "r"(a0), "r"(a1), "r"(a2), "r"(a3), "r"(b0), "r"(b1));
}

// ===========================================================================
// Plain-tf32 GEMM: C[m][n] = sum_k A[m][k]*W[n][k] + bias[n]
// Block tile 128(M) x 128(N), K-chunk 32, 256 threads = 8 warps (2m x 4n),
// warp tile 64x32. Double-buffered smem + register-staged gmem prefetch.
// launch_bounds(256,2): ~120 live regs -> 2 CTAs/SM = 16 warps, hiding
// LDS/MMA latency that capped tensor util at 46% with 8 warps.
// Per-thread accumulation order identical to round 12 -> bit-identical C.
// MODE 0: scatter epilogue into g_q/g_k/g_v; MODE 1: plain row-major store.
// ===========================================================================
#define ST   36
#define BUFW (256*ST)                 // words per buffer (128 A-rows + 128 W-rows)
#define G2_SMEM (2*BUFW*4)            // 73,728 B per CTA -> 2 CTAs/SM

__device__ __forceinline__ void ld_chunk(const float* Ap, const float* Wp,
                                         int Kd, int koff,
                                         float4* ra, float4* rw)
{
    #pragma unroll
    for (int p = 0; p < 4; p++)
        ra[p] = *reinterpret_cast<const float4*>(Ap + (size_t)p*32*Kd + koff);
    #pragma unroll
    for (int p = 0; p < 4; p++)
        rw[p] = *reinterpret_cast<const float4*>(Wp + (size_t)p*32*Kd + koff);
}
__device__ __forceinline__ void st_chunk(uint32_t* As, uint32_t* Ws, int wbase,
                                         const float4* ra, const float4* rw)
{
    #pragma unroll
    for (int p = 0; p < 4; p++)
        *reinterpret_cast<uint4*>(&As[wbase + p*32*ST]) =
            make_uint4(f2tf(ra[p].x), f2tf(ra[p].y), f2tf(ra[p].z), f2tf(ra[p].w));
    #pragma unroll
    for (int p = 0; p < 4; p++)
        *reinterpret_cast<uint4*>(&Ws[wbase + p*32*ST]) =
            make_uint4(f2tf(rw[p].x), f2tf(rw[p].y), f2tf(rw[p].z), f2tf(rw[p].w));
}

template<int MODE>
__global__ __launch_bounds__(256, 2) void gemm2_tf32(
    const float* __restrict__ A, const float* __restrict__ W,
    const float* __restrict__ bias, float* __restrict__ Cplain, int Ncols)
{
    extern __shared__ uint32_t sh[];

    const int tid  = threadIdx.x;
    const int lane = tid & 31, w = tid >> 5;
    const int g = lane >> 2, tg = lane & 3;
    const int wm = w & 1, wn = w >> 1;            // 2 x 4 warp grid
    const int m0 = blockIdx.x << 7, n0 = blockIdx.y << 7;
    const int Kdim = Ec;

    float acc[4][4][4];
    #pragma unroll
    for (int i = 0; i < 4; i++)
        #pragma unroll
        for (int j = 0; j < 4; j++)
            #pragma unroll
            for (int r = 0; r < 4; r++) acc[i][j][r] = 0.0f;

    const int lr = tid >> 3;             // 0..31
    const int lc = (tid & 7) << 2;       // 0..28
    const float* Ap = A + (size_t)(m0 + lr) * Kdim + lc;
    const float* Wp = W + (size_t)(n0 + lr) * Kdim + lc;
    const int wbase = lr * ST + lc;

    float4 ra[4], rw[4];
    ld_chunk(Ap, Wp, Kdim, 0, ra, rw);
    st_chunk(sh, sh + 128*ST, wbase, ra, rw);
    __syncthreads();

    const int nch = Kdim / 32;
    for (int c = 0; c < nch; c++) {
        uint32_t* As = sh + (c & 1) * BUFW;
        uint32_t* Ws = As + 128*ST;
        const bool more = (c + 1 < nch);
        if (more) ld_chunk(Ap, Wp, Kdim, (c + 1) * 32, ra, rw);

        #pragma unroll
        for (int ks = 0; ks < 4; ks++) {
            const int kk = ks * 8;
            uint32_t bf[4][2];
            #pragma unroll
            for (int j = 0; j < 4; j++) {
                const int br = (wn*32 + j*8 + g)*ST + kk + tg;
                bf[j][0] = Ws[br]; bf[j][1] = Ws[br + 4];
            }
            #pragma unroll
            for (int i = 0; i < 4; i++) {
                const int ar = (wm*64 + i*16 + g)*ST + kk + tg;
                uint32_t a0 = As[ar],     a1 = As[ar + 8*ST];
                uint32_t a2 = As[ar + 4], a3 = As[ar + 8*ST + 4];
                #pragma unroll
                for (int j = 0; j < 4; j++)
                    mma8(acc[i][j], a0, a1, a2, a3, bf[j][0], bf[j][1]);
            }
        }

        if (more) {
            uint32_t* Asn = sh + ((c + 1) & 1) * BUFW;
            st_chunk(Asn, Asn + 128*ST, wbase, ra, rw);
            __syncthreads();
        }
    }

    #pragma unroll
    for (int i = 0; i < 4; i++) {
        const int mlo = m0 + wm*64 + i*16 + g;
        #pragma unroll
        for (int j = 0; j < 4; j++) {
            const int n = n0 + wn*32 + j*8 + 2*tg;
            const float b0 = __ldg(&bias[n]), b1 = __ldg(&bias[n+1]);
            #pragma unroll
            for (int half = 0; half < 2; half++) {
                const int m = mlo + half*8;
                const float v0 = acc[i][j][half*2+0] + b0;
                const float v1 = acc[i][j][half*2+1] + b1;
                if (MODE == 0) {
                    const int h = n / 192, r = n - h*192;
                    const int part = r >> 6, d = r & 63;
                    const int b = m >> 11, s = m & 2047;
                    float* dst = (part == 0) ? g_q : (part == 1) ? g_k : g_v;
                    *reinterpret_cast<float2*>(&dst[(((b*Hc + h)*Sc) + s)*HDc + d]) =
                        make_float2(v0, v1);
                } else {
                    *reinterpret_cast<float2*>(&Cplain[(size_t)m*Ncols + n]) =
                        make_float2(v0, v1);
                }
            }
        }
    }
}

// ===========================================================================
// Flash attention, tf32 mma.sync. BQ=256 q-rows, 512 threads (16 warps),
// 1 CTA/SM. Per-warp code identical to the verified round-15 kernel; twice
// the q-rows amortize each K/V tile load+convert+barrier -> per-key phase
// overhead halves. Coarser tile-skip (kstart=4*jq) only adds fully-masked
// tiles, which the online-softmax rescale zeroes EXACTLY (sc==0) -> output
// bit-identical to round 15.
//   - Q in smem pre-scaled by 1/8 (exact), K/V reg-prefetch before barrier,
//     P C-frag -> A-frag via lane shuffles (exact).
// ===========================================================================
#define AST 68
#define BQ  256
#define TK  64
#define ATTN_SMEM ((BQ + TK + TK) * AST * 4)   // 104,448 B

__global__ __launch_bounds__(512, 1) void attn_tf32()
{
    extern __shared__ uint32_t sm[];
    uint32_t* Qs = sm;                  // BQ*AST
    uint32_t* Ks = Qs + BQ*AST;         // TK*AST
    uint32_t* Vs = Ks + TK*AST;         // TK*AST

    const int tid  = threadIdx.x;
    const int lane = tid & 31, w = tid >> 5;     // w = 0..15
    const int g = lane >> 2, tg = lane & 3;
    const int bx = blockIdx.x;
    // descending-work order: heavy tiles (jq=7 full scan, jq=0: 32 tiles) first
    const int jq = (bx == 0) ? (Sc/BQ - 1) : bx - 1;
    const int bh = blockIdx.y;          // 0..31

    const float* Qg = g_q + (size_t)bh * Sc * HDc;
    const float* Kg = g_k + (size_t)bh * Sc * HDc;
    const float* Vg = g_v + (size_t)bh * Sc * HDc;

    // Load Q tile (256 x 64), pre-scaled by 1/8 (exact)
    #pragma unroll
    for (int p = 0; p < 8; p++) {
        const int idx = tid + p*512;
        const int r = idx >> 4, c = (idx & 15) << 2;
        float4 v = *reinterpret_cast<const float4*>(Qg + (size_t)(jq*BQ + r)*HDc + c);
        *reinterpret_cast<uint4*>(&Qs[r*AST + c]) =
            make_uint4(f2tf(0.125f*v.x), f2tf(0.125f*v.y),
                       f2tf(0.125f*v.z), f2tf(0.125f*v.w));
    }

    float m_i[2] = {-INFINITY, -INFINITY};
    float l_i[2] = {0.0f, 0.0f};
    float O[8][4];
    #pragma unroll
    for (int j = 0; j < 8; j++)
        #pragma unroll
        for (int r = 0; r < 4; r++) O[j][r] = 0.0f;

    const int r0   = w * 16;
    const int qrow = jq*BQ + r0 + g;

    // shuffle sources for the P C-frag -> A-frag permutation
    const int srcA = (lane & ~3) | (tg >> 1);   // cols tg
    const int srcB = srcA + 2;                  // cols tg+4
    const bool odd = (tg & 1) != 0;

    const int kstart = (jq == (Sc/BQ - 1)) ? 0 : 4*jq;

    for (int jk = kstart; jk < Sc/TK; jk++) {
        // Prefetch K/V tile into registers BEFORE the barrier
        float4 kreg[2], vreg[2];
        #pragma unroll
        for (int p = 0; p < 2; p++) {
            const int idx = tid + p*512;
            const int r = idx >> 4, c = (idx & 15) << 2;
            kreg[p] = *reinterpret_cast<const float4*>(Kg + (size_t)(jk*TK + r)*HDc + c);
            vreg[p] = *reinterpret_cast<const float4*>(Vg + (size_t)(jk*TK + r)*HDc + c);
        }
        __syncthreads();   // prior-iter smem reads done (covers Q store on iter 1)
        #pragma unroll
        for (int p = 0; p < 2; p++) {
            const int idx = tid + p*512;
            const int r = idx >> 4, c = (idx & 15) << 2;
            *reinterpret_cast<uint4*>(&Ks[r*AST + c]) =
                make_uint4(f2tf(kreg[p].x), f2tf(kreg[p].y),
                           f2tf(kreg[p].z), f2tf(kreg[p].w));
            *reinterpret_cast<uint4*>(&Vs[r*AST + c]) =
                make_uint4(f2tf(vreg[p].x), f2tf(vreg[p].y),
                           f2tf(vreg[p].z), f2tf(vreg[p].w));
        }
        __syncthreads();

        // S = (Q/8) K^T : warp rows r0..r0+15, all 64 cols (already scaled)
        float S[8][4];
        #pragma unroll
        for (int j = 0; j < 8; j++)
            #pragma unroll
            for (int r = 0; r < 4; r++) S[j][r] = 0.0f;

        #pragma unroll
        for (int ks = 0; ks < 8; ks++) {
            const int kk = ks*8;
            const int ar = (r0 + g)*AST + kk + tg;
            const uint32_t a0 = Qs[ar],     a1 = Qs[ar + 8*AST];
            const uint32_t a2 = Qs[ar + 4], a3 = Qs[ar + 8*AST + 4];
            #pragma unroll
            for (int j = 0; j < 8; j++) {
                const int br = (j*8 + g)*AST + kk + tg;
                mma8(S[j], a0, a1, a2, a3, Ks[br], Ks[br + 4]);
            }
        }

        // mask (tril incl diagonal gets -1e9; S already carries the 1/8 scale)
        const int qlo = qrow, qhi = qrow + 8;
        #pragma unroll
        for (int j = 0; j < 8; j++) {
            const int c0 = jk*TK + j*8 + 2*tg;
            S[j][0] += ((c0    ) <= qlo ? NEGBIG : 0.0f);
            S[j][1] += ((c0 + 1) <= qlo ? NEGBIG : 0.0f);
            S[j][2] += ((c0    ) <= qhi ? NEGBIG : 0.0f);
            S[j][3] += ((c0 + 1) <= qhi ? NEGBIG : 0.0f);
        }

        // online softmax (rows live in lanes sharing g; reduce over tg via xor)
        float rm0 = -INFINITY, rm1 = -INFINITY;
        #pragma unroll
        for (int j = 0; j < 8; j++) {
            rm0 = fmaxf(rm0, fmaxf(S[j][0], S[j][1]));
            rm1 = fmaxf(rm1, fmaxf(S[j][2], S[j][3]));
        }
        rm0 = fmaxf(rm0, __shfl_xor_sync(FULLM, rm0, 1));
        rm0 = fmaxf(rm0, __shfl_xor_sync(FULLM, rm0, 2));
        rm1 = fmaxf(rm1, __shfl_xor_sync(FULLM, rm1, 1));
        rm1 = fmaxf(rm1, __shfl_xor_sync(FULLM, rm1, 2));

        const float mn0 = fmaxf(m_i[0], rm0), mn1 = fmaxf(m_i[1], rm1);
        const float sc0 = __expf(m_i[0] - mn0), sc1 = __expf(m_i[1] - mn1);
        l_i[0] *= sc0; l_i[1] *= sc1;

        float rs0 = 0.0f, rs1 = 0.0f;
        #pragma unroll
        for (int j = 0; j < 8; j++) {
            O[j][0] *= sc0; O[j][1] *= sc0; O[j][2] *= sc1; O[j][3] *= sc1;
            S[j][0] = __expf(S[j][0] - mn0); rs0 += S[j][0];
            S[j][1] = __expf(S[j][1] - mn0); rs0 += S[j][1];
            S[j][2] = __expf(S[j][2] - mn1); rs1 += S[j][2];
            S[j][3] = __expf(S[j][3] - mn1); rs1 += S[j][3];
        }
        rs0 += __shfl_xor_sync(FULLM, rs0, 1);
        rs0 += __shfl_xor_sync(FULLM, rs0, 2);
        rs1 += __shfl_xor_sync(FULLM, rs1, 1);
        rs1 += __shfl_xor_sync(FULLM, rs1, 2);
        l_i[0] += rs0; l_i[1] += rs1;
        m_i[0] = mn0;  m_i[1] = mn1;

        // O += P V : per k-group, permute P C-frag -> A-frag via shuffles.
        #pragma unroll
        for (int js = 0; js < 8; js++) {
            const uint32_t t0 = f2tf(S[js][0]), t1 = f2tf(S[js][1]);
            const uint32_t t2 = f2tf(S[js][2]), t3 = f2tf(S[js][3]);
            const uint32_t u0 = __shfl_sync(FULLM, t0, srcA);
            const uint32_t u1 = __shfl_sync(FULLM, t1, srcA);
            const uint32_t u2 = __shfl_sync(FULLM, t2, srcA);
            const uint32_t u3 = __shfl_sync(FULLM, t3, srcA);
            const uint32_t v0 = __shfl_sync(FULLM, t0, srcB);
            const uint32_t v1 = __shfl_sync(FULLM, t1, srcB);
            const uint32_t v2 = __shfl_sync(FULLM, t2, srcB);
            const uint32_t v3 = __shfl_sync(FULLM, t3, srcB);
            const uint32_t pa0 = odd ? u1 : u0;
            const uint32_t pa1 = odd ? u3 : u2;
            const uint32_t pa2 = odd ? v1 : v0;
            const uint32_t pa3 = odd ? v3 : v2;
            const int kk = js*8;
            #pragma unroll
            for (int j = 0; j < 8; j++) {
                const int nb = j*8 + g;
                mma8(O[j], pa0, pa1, pa2, pa3,
                     Vs[(kk + tg)*AST + nb], Vs[(kk + tg + 4)*AST + nb]);
            }
        }
    }

    // normalize + store to g_vals [B,S,E], E index = h*64 + d
    const int b = bh >> 4, h = bh & 15;
    const float inv0 = 1.0f / l_i[0], inv1 = 1.0f / l_i[1];
    const size_t base0 = ((size_t)(b*Sc + qrow))*Ec + h*HDc;
    const size_t base1 = ((size_t)(b*Sc + qrow + 8))*Ec + h*HDc;
    #pragma unroll
    for (int j = 0; j < 8; j++) {
        const int c = j*8 + 2*tg;
        *reinterpret_cast<float2*>(&g_vals[base0 + c]) =
            make_float2(O[j][0]*inv0, O[j][1]*inv0);
        *reinterpret_cast<float2*>(&g_vals[base1 + c]) =
            make_float2(O[j][2]*inv1, O[j][3]*inv1);
    }
}

// ---------------------------------------------------------------------------
extern "C" void kernel_launch(void* const* d_in, const int* in_sizes, int n_in,
                              void* d_out, int out_size)
{
    const float* x    = (const float*)d_in[0];
    const float* Wqkv = (const float*)d_in[1];
    const float* bqkv = (const float*)d_in[2];
    const float* Wout = (const float*)d_in[3];
    const float* bout = (const float*)d_in[4];
    float* out = (float*)d_out;

    float* valsp = nullptr;
    cudaGetSymbolAddress((void**)&valsp, g_vals);

    cudaFuncSetAttribute(gemm2_tf32<0>,
                         cudaFuncAttributeMaxDynamicSharedMemorySize, G2_SMEM);
    cudaFuncSetAttribute(gemm2_tf32<1>,
                         cudaFuncAttributeMaxDynamicSharedMemorySize, G2_SMEM);
    cudaFuncSetAttribute(attn_tf32,
                         cudaFuncAttributeMaxDynamicSharedMemorySize, ATTN_SMEM);

    // 1) QKV projection (plain tf32, 128x128 tiles, 2 CTAs/SM) -> g_q/g_k/g_v
    gemm2_tf32<0><<<dim3(Mrows/128, (3*Ec)/128), 256, G2_SMEM>>>(
        x, Wqkv, bqkv, nullptr, 0);

    // 2) Attention -> g_vals [B,S,E]  (BQ=256, 512 threads, 16 warps/SM)
    attn_tf32<<<dim3(Sc/BQ, Bc*Hc), 512, ATTN_SMEM>>>();

    // 3) Output projection (plain tf32) -> d_out
    gemm2_tf32<1><<<dim3(Mrows/128, Ec/128), 256, G2_SMEM>>>(
        valsp, Wout, bout, out, Ec);
}

// round 17
// speedup vs baseline: 1.0728x; 1.0728x over previous
#include <cuda_runtime.h>
#include <cuda_bf16.h>
#include <math.h>
#include <stdint.h>

// Problem constants
#define Bc   2
#define Sc   2048
#define Ec   1024
#define Hc   16
#define HDc  64
#define Mrows (Bc*Sc)          // 4096
#define NEGBIG (-1.0e9f)
#define FULLM 0xffffffffu

// Scratch (device globals; no allocation allowed)
__device__ float g_q[Bc*Hc*Sc*HDc];     // [B,H,S,HD]
__device__ float g_k[Bc*Hc*Sc*HDc];
__device__ float g_v[Bc*Hc*Sc*HDc];
__device__ float g_vals[Mrows*Ec];      // [B,S,E]

// ---------------------------------------------------------------------------
// mma.sync helpers
// ---------------------------------------------------------------------------
__device__ __forceinline__ uint32_t f2tf(float x) {
    uint32_t r;
    asm("cvt.rna.tf32.f32 %0, %1;" : "=r"(r) : "f"(x));
    return r;
}
__device__ __forceinline__ void mma8(float* c,
    uint32_t a0, uint32_t a1, uint32_t a2, uint32_t a3,
    uint32_t b0, uint32_t b1)
{
    asm volatile(
        "mma.sync.aligned.m16n8k8.row.col.f32.tf32.tf32.f32 "
        "{%0,%1,%2,%3},{%4,%5,%6,%7},{%8,%9},{%0,%1,%2,%3};"
        : "+f"(c[0]), "+f"(c[1]), "+f"(c[2]), "+f"(c[3])
        : "r"(a0), "r"(a1), "r"(a2), "r"(a3), "r"(b0), "r"(b1));
}

// ===========================================================================
// Plain-tf32 GEMM — EXACT round-15 version (verified: QKV 182us, out 74us).
// Block tile 128(M) x 256(N), K-chunk 32, 8 warps, warp tile 64x64,
// double-buffered smem + register-staged gmem prefetch.
// MODE 0: scatter epilogue into g_q/g_k/g_v; MODE 1: plain row-major store.
// ===========================================================================
#define ST   36
#define BUFW (384*ST)
#define G2_SMEM (2*BUFW*4)

__device__ __forceinline__ void ld_chunk(const float* Ap, const float* Wp,
                                         int Kd, int koff,
                                         float4* ra, float4* rw)
{
    #pragma unroll
    for (int p = 0; p < 4; p++)
        ra[p] = *reinterpret_cast<const float4*>(Ap + (size_t)p*32*Kd + koff);
    #pragma unroll
    for (int p = 0; p < 8; p++)
        rw[p] = *reinterpret_cast<const float4*>(Wp + (size_t)p*32*Kd + koff);
}
__device__ __forceinline__ void st_chunk(uint32_t* As, uint32_t* Ws, int wbase,
                                         const float4* ra, const float4* rw)
{
    #pragma unroll
    for (int p = 0; p < 4; p++)
        *reinterpret_cast<uint4*>(&As[wbase + p*32*ST]) =
            make_uint4(f2tf(ra[p].x), f2tf(ra[p].y), f2tf(ra[p].z), f2tf(ra[p].w));
    #pragma unroll
    for (int p = 0; p < 8; p++)
        *reinterpret_cast<uint4*>(&Ws[wbase + p*32*ST]) =
            make_uint4(f2tf(rw[p].x), f2tf(rw[p].y), f2tf(rw[p].z), f2tf(rw[p].w));
}

template<int MODE>
__global__ __launch_bounds__(256, 1) void gemm2_tf32(
    const float* __restrict__ A, const float* __restrict__ W,
    const float* __restrict__ bias, float* __restrict__ Cplain, int Ncols)
{
    extern __shared__ uint32_t sh[];

    const int tid  = threadIdx.x;
    const int lane = tid & 31, w = tid >> 5;
    const int g = lane >> 2, tg = lane & 3;
    const int wm = w & 1, wn = w >> 1;
    const int m0 = blockIdx.x << 7, n0 = blockIdx.y << 8;
    const int Kdim = Ec;

    float acc[4][8][4];
    #pragma unroll
    for (int i = 0; i < 4; i++)
        #pragma unroll
        for (int j = 0; j < 8; j++)
            #pragma unroll
            for (int r = 0; r < 4; r++) acc[i][j][r] = 0.0f;

    const int lr = tid >> 3;
    const int lc = (tid & 7) << 2;
    const float* Ap = A + (size_t)(m0 + lr) * Kdim + lc;
    const float* Wp = W + (size_t)(n0 + lr) * Kdim + lc;
    const int wbase = lr * ST + lc;

    float4 ra[4], rw[8];
    ld_chunk(Ap, Wp, Kdim, 0, ra, rw);
    st_chunk(sh, sh + 128*ST, wbase, ra, rw);
    __syncthreads();

    const int nch = Kdim / 32;
    for (int c = 0; c < nch; c++) {
        uint32_t* As = sh + (c & 1) * BUFW;
        uint32_t* Ws = As + 128*ST;
        const bool more = (c + 1 < nch);
        if (more) ld_chunk(Ap, Wp, Kdim, (c + 1) * 32, ra, rw);

        #pragma unroll
        for (int ks = 0; ks < 4; ks++) {
            const int kk = ks * 8;
            uint32_t bf[8][2];
            #pragma unroll
            for (int j = 0; j < 8; j++) {
                const int br = (wn*64 + j*8 + g)*ST + kk + tg;
                bf[j][0] = Ws[br]; bf[j][1] = Ws[br + 4];
            }
            #pragma unroll
            for (int i = 0; i < 4; i++) {
                const int ar = (wm*64 + i*16 + g)*ST + kk + tg;
                uint32_t a0 = As[ar],     a1 = As[ar + 8*ST];
                uint32_t a2 = As[ar + 4], a3 = As[ar + 8*ST + 4];
                #pragma unroll
                for (int j = 0; j < 8; j++)
                    mma8(acc[i][j], a0, a1, a2, a3, bf[j][0], bf[j][1]);
            }
        }

        if (more) {
            uint32_t* Asn = sh + ((c + 1) & 1) * BUFW;
            st_chunk(Asn, Asn + 128*ST, wbase, ra, rw);
            __syncthreads();
        }
    }

    #pragma unroll
    for (int i = 0; i < 4; i++) {
        const int mlo = m0 + wm*64 + i*16 + g;
        #pragma unroll
        for (int j = 0; j < 8; j++) {
            const int n = n0 + wn*64 + j*8 + 2*tg;
            const float b0 = __ldg(&bias[n]), b1 = __ldg(&bias[n+1]);
            #pragma unroll
            for (int half = 0; half < 2; half++) {
                const int m = mlo + half*8;
                const float v0 = acc[i][j][half*2+0] + b0;
                const float v1 = acc[i][j][half*2+1] + b1;
                if (MODE == 0) {
                    const int h = n / 192, r = n - h*192;
                    const int part = r >> 6, d = r & 63;
                    const int b = m >> 11, s = m & 2047;
                    float* dst = (part == 0) ? g_q : (part == 1) ? g_k : g_v;
                    *reinterpret_cast<float2*>(&dst[(((b*Hc + h)*Sc) + s)*HDc + d]) =
                        make_float2(v0, v1);
                } else {
                    *reinterpret_cast<float2*>(&Cplain[(size_t)m*Ncols + n]) =
                        make_float2(v0, v1);
                }
            }
        }
    }
}

// ===========================================================================
// Flash attention, tf32 mma.sync. BQ=128, 256 threads, 2 CTAs/SM (R15 base)
// + DOUBLE-BUFFERED K/V smem with ONE barrier per tile:
//   iter jk: [QK+softmax+PV on buf pb] [LDG jk+1 after QK] [STS jk+1 -> pb^1]
//            [__syncthreads]
//   Safety: buf pb^1 was last READ during iter jk-1; every warp passed the
//   sync at the end of jk-1 before entering jk, so compute(jk-1) is globally
//   complete when any warp stores into pb^1 during jk. One sync suffices.
// vs R15 (LDG -> sync -> STS -> sync -> compute): halves barrier count and
// lets stores overlap other warps' compute. Arithmetic identical -> output
// bit-identical (rel_err must stay 0.0006054936).
// ===========================================================================
#define AST 68
#define BQ  128
#define TK  64
#define ATTN_SMEM ((BQ + 4*TK) * AST * 4)   // 104,448 B; x2 CTAs = 204 KB/SM

__global__ __launch_bounds__(256, 2) void attn_tf32()
{
    extern __shared__ uint32_t sm[];
    uint32_t* Qs  = sm;                      // BQ*AST
    uint32_t* KV0 = Qs + BQ*AST;             // [K0 | V0] : 2*TK*AST
    uint32_t* KV1 = KV0 + 2*TK*AST;          // [K1 | V1]

    const int tid  = threadIdx.x;
    const int lane = tid & 31, w = tid >> 5;
    const int g = lane >> 2, tg = lane & 3;
    const int bx = blockIdx.x;
    // descending-work order: heavy tiles (jq=15 full scan, jq=0: 32 tiles) first
    const int jq = (bx == 0) ? (Sc/BQ - 1) : bx - 1;
    const int bh = blockIdx.y;          // 0..31

    const float* Qg = g_q + (size_t)bh * Sc * HDc;
    const float* Kg = g_k + (size_t)bh * Sc * HDc;
    const float* Vg = g_v + (size_t)bh * Sc * HDc;

    // Load Q tile (128 x 64), pre-scaled by 1/8 (exact)
    #pragma unroll
    for (int p = 0; p < 8; p++) {
        const int idx = tid + p*256;
        const int r = idx >> 4, c = (idx & 15) << 2;
        float4 v = *reinterpret_cast<const float4*>(Qg + (size_t)(jq*BQ + r)*HDc + c);
        *reinterpret_cast<uint4*>(&Qs[r*AST + c]) =
            make_uint4(f2tf(0.125f*v.x), f2tf(0.125f*v.y),
                       f2tf(0.125f*v.z), f2tf(0.125f*v.w));
    }

    float m_i[2] = {-INFINITY, -INFINITY};
    float l_i[2] = {0.0f, 0.0f};
    float O[8][4];
    #pragma unroll
    for (int j = 0; j < 8; j++)
        #pragma unroll
        for (int r = 0; r < 4; r++) O[j][r] = 0.0f;

    const int r0   = w * 16;
    const int qrow = jq*BQ + r0 + g;

    // shuffle sources for the P C-frag -> A-frag permutation
    const int srcA = (lane & ~3) | (tg >> 1);   // cols tg
    const int srcB = srcA + 2;                  // cols tg+4
    const bool odd = (tg & 1) != 0;

    const int kstart = (jq == (Sc/BQ - 1)) ? 0 : 2*jq;
    const int nk = Sc/TK;

    // Prologue: first K/V tile into buffer 0 (no hazard: buffers unread yet;
    // the single sync also publishes the Q store).
    {
        #pragma unroll
        for (int p = 0; p < 4; p++) {
            const int idx = tid + p*256;
            const int r = idx >> 4, c = (idx & 15) << 2;
            float4 kv = *reinterpret_cast<const float4*>(Kg + (size_t)(kstart*TK + r)*HDc + c);
            float4 vv = *reinterpret_cast<const float4*>(Vg + (size_t)(kstart*TK + r)*HDc + c);
            *reinterpret_cast<uint4*>(&KV0[r*AST + c]) =
                make_uint4(f2tf(kv.x), f2tf(kv.y), f2tf(kv.z), f2tf(kv.w));
            *reinterpret_cast<uint4*>(&KV0[TK*AST + r*AST + c]) =
                make_uint4(f2tf(vv.x), f2tf(vv.y), f2tf(vv.z), f2tf(vv.w));
        }
    }
    __syncthreads();

    int pb = 0;
    for (int jk = kstart; jk < nk; jk++, pb ^= 1) {
        uint32_t* Ks = pb ? KV1 : KV0;
        uint32_t* Vs = Ks + TK*AST;
        const bool more = (jk + 1 < nk);

        // S = (Q/8) K^T : warp rows r0..r0+15, all 64 cols (already scaled)
        float S[8][4];
        #pragma unroll
        for (int j = 0; j < 8; j++)
            #pragma unroll
            for (int r = 0; r < 4; r++) S[j][r] = 0.0f;

        #pragma unroll
        for (int ks = 0; ks < 8; ks++) {
            const int kk = ks*8;
            const int ar = (r0 + g)*AST + kk + tg;
            const uint32_t a0 = Qs[ar],     a1 = Qs[ar + 8*AST];
            const uint32_t a2 = Qs[ar + 4], a3 = Qs[ar + 8*AST + 4];
            #pragma unroll
            for (int j = 0; j < 8; j++) {
                const int br = (j*8 + g)*AST + kk + tg;
                mma8(S[j], a0, a1, a2, a3, Ks[br], Ks[br + 4]);
            }
        }

        // Prefetch next K/V tile (LDG) — softmax+PV (~1500 cyc) hides latency
        float4 kreg[4], vreg[4];
        if (more) {
            #pragma unroll
            for (int p = 0; p < 4; p++) {
                const int idx = tid + p*256;
                const int r = idx >> 4, c = (idx & 15) << 2;
                kreg[p] = *reinterpret_cast<const float4*>(Kg + (size_t)((jk+1)*TK + r)*HDc + c);
                vreg[p] = *reinterpret_cast<const float4*>(Vg + (size_t)((jk+1)*TK + r)*HDc + c);
            }
        }

        // mask (tril incl diagonal gets -1e9; S already carries the 1/8 scale)
        const int qlo = qrow, qhi = qrow + 8;
        #pragma unroll
        for (int j = 0; j < 8; j++) {
            const int c0 = jk*TK + j*8 + 2*tg;
            S[j][0] += ((c0    ) <= qlo ? NEGBIG : 0.0f);
            S[j][1] += ((c0 + 1) <= qlo ? NEGBIG : 0.0f);
            S[j][2] += ((c0    ) <= qhi ? NEGBIG : 0.0f);
            S[j][3] += ((c0 + 1) <= qhi ? NEGBIG : 0.0f);
        }

        // online softmax (rows live in lanes sharing g; reduce over tg via xor)
        float rm0 = -INFINITY, rm1 = -INFINITY;
        #pragma unroll
        for (int j = 0; j < 8; j++) {
            rm0 = fmaxf(rm0, fmaxf(S[j][0], S[j][1]));
            rm1 = fmaxf(rm1, fmaxf(S[j][2], S[j][3]));
        }
        rm0 = fmaxf(rm0, __shfl_xor_sync(FULLM, rm0, 1));
        rm0 = fmaxf(rm0, __shfl_xor_sync(FULLM, rm0, 2));
        rm1 = fmaxf(rm1, __shfl_xor_sync(FULLM, rm1, 1));
        rm1 = fmaxf(rm1, __shfl_xor_sync(FULLM, rm1, 2));

        const float mn0 = fmaxf(m_i[0], rm0), mn1 = fmaxf(m_i[1], rm1);
        const float sc0 = __expf(m_i[0] - mn0), sc1 = __expf(m_i[1] - mn1);
        l_i[0] *= sc0; l_i[1] *= sc1;

        float rs0 = 0.0f, rs1 = 0.0f;
        #pragma unroll
        for (int j = 0; j < 8; j++) {
            O[j][0] *= sc0; O[j][1] *= sc0; O[j][2] *= sc1; O[j][3] *= sc1;
            S[j][0] = __expf(S[j][0] - mn0); rs0 += S[j][0];
            S[j][1] = __expf(S[j][1] - mn0); rs0 += S[j][1];
            S[j][2] = __expf(S[j][2] - mn1); rs1 += S[j][2];
            S[j][3] = __expf(S[j][3] - mn1); rs1 += S[j][3];
        }
        rs0 += __shfl_xor_sync(FULLM, rs0, 1);
        rs0 += __shfl_xor_sync(FULLM, rs0, 2);
        rs1 += __shfl_xor_sync(FULLM, rs1, 1);
        rs1 += __shfl_xor_sync(FULLM, rs1, 2);
        l_i[0] += rs0; l_i[1] += rs1;
        m_i[0] = mn0;  m_i[1] = mn1;

        // O += P V : per k-group, permute P C-frag -> A-frag via shuffles.
        #pragma unroll
        for (int js = 0; js < 8; js++) {
            const uint32_t t0 = f2tf(S[js][0]), t1 = f2tf(S[js][1]);
            const uint32_t t2 = f2tf(S[js][2]), t3 = f2tf(S[js][3]);
            const uint32_t u0 = __shfl_sync(FULLM, t0, srcA);
            const uint32_t u1 = __shfl_sync(FULLM, t1, srcA);
            const uint32_t u2 = __shfl_sync(FULLM, t2, srcA);
            const uint32_t u3 = __shfl_sync(FULLM, t3, srcA);
            const uint32_t v0 = __shfl_sync(FULLM, t0, srcB);
            const uint32_t v1 = __shfl_sync(FULLM, t1, srcB);
            const uint32_t v2 = __shfl_sync(FULLM, t2, srcB);
            const uint32_t v3 = __shfl_sync(FULLM, t3, srcB);
            const uint32_t pa0 = odd ? u1 : u0;
            const uint32_t pa1 = odd ? u3 : u2;
            const uint32_t pa2 = odd ? v1 : v0;
            const uint32_t pa3 = odd ? v3 : v2;
            const int kk = js*8;
            #pragma unroll
            for (int j = 0; j < 8; j++) {
                const int nb = j*8 + g;
                mma8(O[j], pa0, pa1, pa2, pa3,
                     Vs[(kk + tg)*AST + nb], Vs[(kk + tg + 4)*AST + nb]);
            }
        }

        // Store next tile into the other buffer; single barrier per tile.
        if (more) {
            uint32_t* Kn = pb ? KV0 : KV1;
            uint32_t* Vn = Kn + TK*AST;
            #pragma unroll
            for (int p = 0; p < 4; p++) {
                const int idx = tid + p*256;
                const int r = idx >> 4, c = (idx & 15) << 2;
                *reinterpret_cast<uint4*>(&Kn[r*AST + c]) =
                    make_uint4(f2tf(kreg[p].x), f2tf(kreg[p].y),
                               f2tf(kreg[p].z), f2tf(kreg[p].w));
                *reinterpret_cast<uint4*>(&Vn[r*AST + c]) =
                    make_uint4(f2tf(vreg[p].x), f2tf(vreg[p].y),
                               f2tf(vreg[p].z), f2tf(vreg[p].w));
            }
            __syncthreads();
        }
    }

    // normalize + store to g_vals [B,S,E], E index = h*64 + d
    const int b = bh >> 4, h = bh & 15;
    const float inv0 = 1.0f / l_i[0], inv1 = 1.0f / l_i[1];
    const size_t base0 = ((size_t)(b*Sc + qrow))*Ec + h*HDc;
    const size_t base1 = ((size_t)(b*Sc + qrow + 8))*Ec + h*HDc;
    #pragma unroll
    for (int j = 0; j < 8; j++) {
        const int c = j*8 + 2*tg;
        *reinterpret_cast<float2*>(&g_vals[base0 + c]) =
            make_float2(O[j][0]*inv0, O[j][1]*inv0);
        *reinterpret_cast<float2*>(&g_vals[base1 + c]) =
            make_float2(O[j][2]*inv1, O[j][3]*inv1);
    }
}

// ---------------------------------------------------------------------------
extern "C" void kernel_launch(void* const* d_in, const int* in_sizes, int n_in,
                              void* d_out, int out_size)
{
    const float* x    = (const float*)d_in[0];
    const float* Wqkv = (const float*)d_in[1];
    const float* bqkv = (const float*)d_in[2];
    const float* Wout = (const float*)d_in[3];
    const float* bout = (const float*)d_in[4];
    float* out = (float*)d_out;

    float* valsp = nullptr;
    cudaGetSymbolAddress((void**)&valsp, g_vals);

    cudaFuncSetAttribute(gemm2_tf32<0>,
                         cudaFuncAttributeMaxDynamicSharedMemorySize, G2_SMEM);
    cudaFuncSetAttribute(gemm2_tf32<1>,
                         cudaFuncAttributeMaxDynamicSharedMemorySize, G2_SMEM);
    cudaFuncSetAttribute(attn_tf32,
                         cudaFuncAttributeMaxDynamicSharedMemorySize, ATTN_SMEM);

    // 1) QKV projection (plain tf32, 128x256 tiles) -> scatter into g_q/g_k/g_v
    gemm2_tf32<0><<<dim3(Mrows/128, (3*Ec)/256), 256, G2_SMEM>>>(
        x, Wqkv, bqkv, nullptr, 0);

    // 2) Attention -> g_vals [B,S,E] (BQ=128, 2 CTAs/SM, double-buffered K/V)
    attn_tf32<<<dim3(Sc/BQ, Bc*Hc), 256, ATTN_SMEM>>>();

    // 3) Output projection (plain tf32) -> d_out
    gemm2_tf32<1><<<dim3(Mrows/128, Ec/256), 256, G2_SMEM>>>(
        valsp, Wout, bout, out, Ec);
}